// round 3
// baseline (speedup 1.0000x reference)
#include <cuda_runtime.h>
#include <math.h>

// ---------------------------------------------------------------------------
// ConnectedFilterLayerWithImplicitJacobian
//   filtered = residues * sigmoid(attrs2d @ w + b)
//   delta[tpre[i]] = filtered[i]; delta[tpost[i]] = -filtered[i]  (permutation)
//   cumsum = inclusive prefix scan of delta (2N)   [single-pass lookback]
//   y_node[i] = cumsum[tpre[i]]                    [per-node gather]
//   out[p]    = y_node[node_of_pixel[p]]           [per-pixel gather, dominant]
// ---------------------------------------------------------------------------

#define TMAX    (1 << 20)         // 2N = 1,000,000 <= 1,048,576
#define NMAX    (1 << 19)         // N = 500,000 <= 524,288
#define STILE   8192
#define STHREADS 512
#define SIPT    (STILE / STHREADS)  // 16

__device__ float g_delta[TMAX];
__device__ float g_cumsum[TMAX];
__device__ float g_ynode[NMAX];
// [0] = ticket counter, [1..] = lookback descriptors (flag<<32 | float bits)
__device__ unsigned long long g_scan_state[256];

#define FLAG_AGG 1u
#define FLAG_PRE 2u

__device__ __forceinline__ unsigned long long pack_desc(float v, unsigned f) {
    return ((unsigned long long)f << 32) | (unsigned long long)__float_as_uint(v);
}

// --------------- kernel 1: filtered + scatter (+ scan-state reset) ---------
__global__ void k_filtered(const float* __restrict__ weight,
                           const float* __restrict__ bias,
                           const float* __restrict__ residues,
                           const float* __restrict__ attrs,
                           const int*   __restrict__ tpre,
                           const int*   __restrict__ tpost,
                           int n, int nstate)
{
    // Block 0 resets the lookback state for this replay (visible to k_scan
    // via the kernel-boundary fence).
    if (blockIdx.x == 0 && threadIdx.x < nstate)
        g_scan_state[threadIdx.x] = 0ull;

    int i = blockIdx.x * blockDim.x + threadIdx.x;
    if (i >= n) return;

    const float4* a = reinterpret_cast<const float4*>(attrs + (size_t)i * 8);
    float4 a0 = a[0];
    float4 a1 = a[1];
    float4 w0 = *reinterpret_cast<const float4*>(weight);
    float4 w1 = *(reinterpret_cast<const float4*>(weight) + 1);

    float logit = a0.x * w0.x + a0.y * w0.y + a0.z * w0.z + a0.w * w0.w
                + a1.x * w1.x + a1.y * w1.y + a1.z * w1.z + a1.w * w1.w
                + bias[0];
    float s = 1.0f / (1.0f + expf(-logit));
    float f = residues[i] * s;

    // tpre ∪ tpost is a permutation of [0, 2N): plain stores, no atomics.
    g_delta[tpre[i]]  =  f;
    g_delta[tpost[i]] = -f;
}

// ------------------------- kernel 2: single-pass lookback scan -------------
__global__ __launch_bounds__(STHREADS) void k_scan(int T)
{
    __shared__ unsigned s_bid;
    __shared__ float    s_excl;
    __shared__ float    s_warp[STHREADS / 32];

    int t = threadIdx.x;
    int lane = t & 31;
    int w = t >> 5;

    if (t == 0) s_bid = atomicAdd((unsigned int*)&g_scan_state[0], 1u);
    __syncthreads();
    int b = (int)s_bid;
    unsigned long long* desc = g_scan_state + 1;

    int base = b * STILE;
    bool full = (base + STILE <= T);

    float e[SIPT];
    if (full) {
        const float4* src = reinterpret_cast<const float4*>(g_delta + base + t * SIPT);
#pragma unroll
        for (int q = 0; q < SIPT / 4; q++) {
            float4 v = src[q];
            e[q*4+0] = v.x; e[q*4+1] = v.y; e[q*4+2] = v.z; e[q*4+3] = v.w;
        }
    } else {
#pragma unroll
        for (int j = 0; j < SIPT; j++) {
            int g = base + t * SIPT + j;
            e[j] = (g < T) ? g_delta[g] : 0.0f;
        }
    }

    // Serial inclusive scan within thread
    float run = 0.0f;
#pragma unroll
    for (int j = 0; j < SIPT; j++) { run += e[j]; e[j] = run; }

    // Warp inclusive scan of per-thread totals
    float incl = run;
#pragma unroll
    for (int o = 1; o < 32; o <<= 1) {
        float nb = __shfl_up_sync(0xffffffffu, incl, o);
        if (lane >= o) incl += nb;
    }
    if (lane == 31) s_warp[w] = incl;
    __syncthreads();
    if (t == 0) {
        float acc = 0.0f;
#pragma unroll
        for (int k = 0; k < STHREADS / 32; k++) { acc += s_warp[k]; s_warp[k] = acc; }
    }
    __syncthreads();
    float thr_excl = incl - run + (w > 0 ? s_warp[w - 1] : 0.0f);
    float block_total = s_warp[STHREADS / 32 - 1];

    if (t == 0) {
        unsigned long long d = (b == 0) ? pack_desc(block_total, FLAG_PRE)
                                        : pack_desc(block_total, FLAG_AGG);
        atomicExch(&desc[b], d);
        if (b == 0) s_excl = 0.0f;
    }

    // Warp-parallel lookback (warp 0)
    if (b > 0 && w == 0) {
        float running = 0.0f;
        int tile_idx = b - 1;
        while (true) {
            int idx = tile_idx - lane;
            unsigned f;
            float val;
            if (idx < 0) { f = FLAG_PRE; val = 0.0f; }
            else {
                unsigned long long d;
                do {
                    d = *((volatile unsigned long long*)&desc[idx]);
                    f = (unsigned)(d >> 32);
                } while (f == 0u);
                val = __uint_as_float((unsigned)(d & 0xffffffffull));
            }
            unsigned pmask = __ballot_sync(0xffffffffu, f == FLAG_PRE);
            if (pmask) {
                int fp = __ffs(pmask) - 1;
                float c = (lane <= fp) ? val : 0.0f;
#pragma unroll
                for (int o = 16; o > 0; o >>= 1) c += __shfl_xor_sync(0xffffffffu, c, o);
                running += c;
                break;
            } else {
                float c = val;
#pragma unroll
                for (int o = 16; o > 0; o >>= 1) c += __shfl_xor_sync(0xffffffffu, c, o);
                running += c;
                tile_idx -= 32;
            }
        }
        if (lane == 0) {
            s_excl = running;
            atomicExch(&desc[b], pack_desc(running + block_total, FLAG_PRE));
        }
    }
    __syncthreads();
    float add = s_excl + thr_excl;

    if (full) {
        float4* dst = reinterpret_cast<float4*>(g_cumsum + base + t * SIPT);
#pragma unroll
        for (int q = 0; q < SIPT / 4; q++) {
            float4 r;
            r.x = e[q*4+0] + add; r.y = e[q*4+1] + add;
            r.z = e[q*4+2] + add; r.w = e[q*4+3] + add;
            dst[q] = r;
        }
    } else {
#pragma unroll
        for (int j = 0; j < SIPT; j++) {
            int g = base + t * SIPT + j;
            if (g < T) g_cumsum[g] = e[j] + add;
        }
    }
}

// ------------------------- kernel 3: per-node gather ------------------------
__global__ void k_ynode(const int* __restrict__ tpre, int n)
{
    int i = (blockIdx.x * blockDim.x + threadIdx.x) * 8;
    if (i + 7 < n) {
        int4 t0 = __ldcs(reinterpret_cast<const int4*>(tpre + i));
        int4 t1 = __ldcs(reinterpret_cast<const int4*>(tpre + i + 4));
        float4 r0, r1;
        r0.x = g_cumsum[t0.x]; r0.y = g_cumsum[t0.y];
        r0.z = g_cumsum[t0.z]; r0.w = g_cumsum[t0.w];
        r1.x = g_cumsum[t1.x]; r1.y = g_cumsum[t1.y];
        r1.z = g_cumsum[t1.z]; r1.w = g_cumsum[t1.w];
        __stcs(reinterpret_cast<float4*>(g_ynode + i), r0);
        __stcs(reinterpret_cast<float4*>(g_ynode + i + 4), r1);
    } else {
        for (int j = i; j < n; j++) g_ynode[j] = g_cumsum[tpre[j]];
    }
}

// ------------------------- kernel 4: per-pixel gather -----------------------
// 16 pixels per thread; streaming hints on nop/out keep L1 lines for g_ynode.
__global__ __launch_bounds__(256) void k_gather(const int* __restrict__ nop,
                                                float* __restrict__ out,
                                                int P)
{
    int i = (blockIdx.x * blockDim.x + threadIdx.x) * 16;
    if (i + 15 < P) {
        int4 n0 = __ldcs(reinterpret_cast<const int4*>(nop + i));
        int4 n1 = __ldcs(reinterpret_cast<const int4*>(nop + i + 4));
        int4 n2 = __ldcs(reinterpret_cast<const int4*>(nop + i + 8));
        int4 n3 = __ldcs(reinterpret_cast<const int4*>(nop + i + 12));
        float4 r0, r1, r2, r3;
        r0.x = g_ynode[n0.x]; r0.y = g_ynode[n0.y];
        r0.z = g_ynode[n0.z]; r0.w = g_ynode[n0.w];
        r1.x = g_ynode[n1.x]; r1.y = g_ynode[n1.y];
        r1.z = g_ynode[n1.z]; r1.w = g_ynode[n1.w];
        r2.x = g_ynode[n2.x]; r2.y = g_ynode[n2.y];
        r2.z = g_ynode[n2.z]; r2.w = g_ynode[n2.w];
        r3.x = g_ynode[n3.x]; r3.y = g_ynode[n3.y];
        r3.z = g_ynode[n3.z]; r3.w = g_ynode[n3.w];
        __stcs(reinterpret_cast<float4*>(out + i),      r0);
        __stcs(reinterpret_cast<float4*>(out + i + 4),  r1);
        __stcs(reinterpret_cast<float4*>(out + i + 8),  r2);
        __stcs(reinterpret_cast<float4*>(out + i + 12), r3);
    } else {
        for (int j = i; j < P; j++) out[j] = g_ynode[nop[j]];
    }
}

// ---------------------------------------------------------------------------
extern "C" void kernel_launch(void* const* d_in, const int* in_sizes, int n_in,
                              void* d_out, int out_size)
{
    const float* weight   = (const float*)d_in[0];
    const float* bias     = (const float*)d_in[1];
    const float* residues = (const float*)d_in[2];
    const float* attrs    = (const float*)d_in[3];
    const int*   tpre     = (const int*)d_in[4];
    const int*   tpost    = (const int*)d_in[5];
    const int*   nop      = (const int*)d_in[6];

    int N = in_sizes[2];
    int P = in_sizes[6];
    int T = 2 * N;
    int nb = (T + STILE - 1) / STILE;     // 123 blocks: single wave

    k_filtered<<<(N + 255) / 256, 256>>>(weight, bias, residues, attrs,
                                         tpre, tpost, N, nb + 1);
    k_scan<<<nb, STHREADS>>>(T);

    int ynt = (N + 7) / 8;
    k_ynode<<<(ynt + 255) / 256, 256>>>(tpre, N);

    int gt = (P + 15) / 16;
    k_gather<<<(gt + 255) / 256, 256>>>(nop, (float*)d_out, P);
}

// round 4
// speedup vs baseline: 1.0699x; 1.0699x over previous
#include <cuda_runtime.h>
#include <math.h>

// ---------------------------------------------------------------------------
// ConnectedFilterLayerWithImplicitJacobian
//   filtered = residues * sigmoid(attrs2d @ w + b)
//   pack[tpre[i]]  = {+f, i}      (tpre ∪ tpost = permutation of [0,2N))
//   pack[tpost[i]] = {-f, -1}
//   scan .x lane with decoupled lookback; at tpre slots scatter final prefix
//   straight into y_node[node].  out[p] = y_node[node_of_pixel[p]].
// ---------------------------------------------------------------------------

#define TMAX     (1 << 20)          // 2N = 1,000,000 <= 1,048,576
#define NMAX     (1 << 19)          // N = 500,000 <= 524,288
#define STILE    8192
#define STHREADS 512
#define SIPT     (STILE / STHREADS) // 16 elements (float2) per thread

__device__ float2 g_pack[TMAX];     // .x = delta value, .y = node id as int bits
__device__ float  g_ynode[NMAX];
// [0] = ticket counter, [1..] = lookback descriptors (flag<<32 | float bits)
__device__ unsigned long long g_scan_state[256];

#define FLAG_AGG 1u
#define FLAG_PRE 2u

__device__ __forceinline__ unsigned long long pack_desc(float v, unsigned f) {
    return ((unsigned long long)f << 32) | (unsigned long long)__float_as_uint(v);
}

// --------------- kernel 1: filtered + packed scatter (+ state reset) -------
__global__ void k_filtered(const float* __restrict__ weight,
                           const float* __restrict__ bias,
                           const float* __restrict__ residues,
                           const float* __restrict__ attrs,
                           const int*   __restrict__ tpre,
                           const int*   __restrict__ tpost,
                           int n, int nstate)
{
    if (blockIdx.x == 0 && threadIdx.x < nstate)
        g_scan_state[threadIdx.x] = 0ull;

    int i = blockIdx.x * blockDim.x + threadIdx.x;
    if (i >= n) return;

    const float4* a = reinterpret_cast<const float4*>(attrs + (size_t)i * 8);
    float4 a0 = a[0];
    float4 a1 = a[1];
    float4 w0 = *reinterpret_cast<const float4*>(weight);
    float4 w1 = *(reinterpret_cast<const float4*>(weight) + 1);

    float logit = a0.x * w0.x + a0.y * w0.y + a0.z * w0.z + a0.w * w0.w
                + a1.x * w1.x + a1.y * w1.y + a1.z * w1.z + a1.w * w1.w
                + bias[0];
    float s = 1.0f / (1.0f + expf(-logit));
    float f = residues[i] * s;

    float2 pre  = make_float2( f, __int_as_float(i));
    float2 post = make_float2(-f, __int_as_float(-1));
    g_pack[tpre[i]]  = pre;
    g_pack[tpost[i]] = post;
}

// ------- kernel 2: single-pass lookback scan + direct ynode scatter --------
__global__ __launch_bounds__(STHREADS) void k_scan(int T)
{
    __shared__ unsigned s_bid;
    __shared__ float    s_excl;
    __shared__ float    s_warp[STHREADS / 32];

    int t = threadIdx.x;
    int lane = t & 31;
    int w = t >> 5;

    if (t == 0) s_bid = atomicAdd((unsigned int*)&g_scan_state[0], 1u);
    __syncthreads();
    int b = (int)s_bid;
    unsigned long long* desc = g_scan_state + 1;

    int base = b * STILE;
    bool full = (base + STILE <= T);

    float e[SIPT];
    int   nd[SIPT];
    if (full) {
        const float4* src = reinterpret_cast<const float4*>(g_pack + base + t * SIPT);
#pragma unroll
        for (int q = 0; q < SIPT / 2; q++) {       // each float4 = 2 packed elems
            float4 v = src[q];
            e[q*2+0]  = v.x;  nd[q*2+0] = __float_as_int(v.y);
            e[q*2+1]  = v.z;  nd[q*2+1] = __float_as_int(v.w);
        }
    } else {
#pragma unroll
        for (int j = 0; j < SIPT; j++) {
            int g = base + t * SIPT + j;
            if (g < T) {
                float2 v = g_pack[g];
                e[j] = v.x;
                nd[j] = __float_as_int(v.y);
            } else {
                e[j] = 0.0f;
                nd[j] = -1;
            }
        }
    }

    // Serial inclusive scan within thread
    float run = 0.0f;
#pragma unroll
    for (int j = 0; j < SIPT; j++) { run += e[j]; e[j] = run; }

    // Warp inclusive scan of per-thread totals
    float incl = run;
#pragma unroll
    for (int o = 1; o < 32; o <<= 1) {
        float nb = __shfl_up_sync(0xffffffffu, incl, o);
        if (lane >= o) incl += nb;
    }
    if (lane == 31) s_warp[w] = incl;
    __syncthreads();
    if (t == 0) {
        float acc = 0.0f;
#pragma unroll
        for (int k = 0; k < STHREADS / 32; k++) { acc += s_warp[k]; s_warp[k] = acc; }
    }
    __syncthreads();
    float thr_excl = incl - run + (w > 0 ? s_warp[w - 1] : 0.0f);
    float block_total = s_warp[STHREADS / 32 - 1];

    if (t == 0) {
        unsigned long long d = (b == 0) ? pack_desc(block_total, FLAG_PRE)
                                        : pack_desc(block_total, FLAG_AGG);
        atomicExch(&desc[b], d);
        if (b == 0) s_excl = 0.0f;
    }

    // Warp-parallel lookback (warp 0)
    if (b > 0 && w == 0) {
        float running = 0.0f;
        int tile_idx = b - 1;
        while (true) {
            int idx = tile_idx - lane;
            unsigned f;
            float val;
            if (idx < 0) { f = FLAG_PRE; val = 0.0f; }
            else {
                unsigned long long d;
                do {
                    d = *((volatile unsigned long long*)&desc[idx]);
                    f = (unsigned)(d >> 32);
                } while (f == 0u);
                val = __uint_as_float((unsigned)(d & 0xffffffffull));
            }
            unsigned pmask = __ballot_sync(0xffffffffu, f == FLAG_PRE);
            if (pmask) {
                int fp = __ffs(pmask) - 1;
                float c = (lane <= fp) ? val : 0.0f;
#pragma unroll
                for (int o = 16; o > 0; o >>= 1) c += __shfl_xor_sync(0xffffffffu, c, o);
                running += c;
                break;
            } else {
                float c = val;
#pragma unroll
                for (int o = 16; o > 0; o >>= 1) c += __shfl_xor_sync(0xffffffffu, c, o);
                running += c;
                tile_idx -= 32;
            }
        }
        if (lane == 0) {
            s_excl = running;
            atomicExch(&desc[b], pack_desc(running + block_total, FLAG_PRE));
        }
    }
    __syncthreads();
    float add = s_excl + thr_excl;

    // Scatter final inclusive prefix directly to y_node at tpre slots.
#pragma unroll
    for (int j = 0; j < SIPT; j++) {
        int node = nd[j];
        if (node >= 0) g_ynode[node] = e[j] + add;
    }
}

// ------------------------- kernel 3: per-pixel gather -----------------------
// 8 pixels/thread, plain cache ops (R2 configuration: best measured, 40.8us).
__global__ __launch_bounds__(256) void k_gather(const int* __restrict__ nop,
                                                float* __restrict__ out,
                                                int P)
{
    int i = (blockIdx.x * blockDim.x + threadIdx.x) * 8;
    if (i + 7 < P) {
        int4 n0 = *reinterpret_cast<const int4*>(nop + i);
        int4 n1 = *reinterpret_cast<const int4*>(nop + i + 4);
        float4 r0, r1;
        r0.x = g_ynode[n0.x];
        r0.y = g_ynode[n0.y];
        r0.z = g_ynode[n0.z];
        r0.w = g_ynode[n0.w];
        r1.x = g_ynode[n1.x];
        r1.y = g_ynode[n1.y];
        r1.z = g_ynode[n1.z];
        r1.w = g_ynode[n1.w];
        *reinterpret_cast<float4*>(out + i)     = r0;
        *reinterpret_cast<float4*>(out + i + 4) = r1;
    } else {
        for (int j = i; j < P; j++) out[j] = g_ynode[nop[j]];
    }
}

// ---------------------------------------------------------------------------
extern "C" void kernel_launch(void* const* d_in, const int* in_sizes, int n_in,
                              void* d_out, int out_size)
{
    const float* weight   = (const float*)d_in[0];
    const float* bias     = (const float*)d_in[1];
    const float* residues = (const float*)d_in[2];
    const float* attrs    = (const float*)d_in[3];
    const int*   tpre     = (const int*)d_in[4];
    const int*   tpost    = (const int*)d_in[5];
    const int*   nop      = (const int*)d_in[6];

    int N = in_sizes[2];
    int P = in_sizes[6];
    int T = 2 * N;
    int nb = (T + STILE - 1) / STILE;     // 123 blocks: single wave

    k_filtered<<<(N + 255) / 256, 256>>>(weight, bias, residues, attrs,
                                         tpre, tpost, N, nb + 1);
    k_scan<<<nb, STHREADS>>>(T);

    int gt = (P + 7) / 8;
    k_gather<<<(gt + 255) / 256, 256>>>(nop, (float*)d_out, P);
}

// round 5
// speedup vs baseline: 1.0753x; 1.0050x over previous
#include <cuda_runtime.h>
#include <math.h>

// ---------------------------------------------------------------------------
// ConnectedFilterLayerWithImplicitJacobian
//   filtered = residues * sigmoid(attrs2d @ w + b)
//   pack[tpre[i]]  = {+f, i}      (tpre ∪ tpost = permutation of [0,2N))
//   pack[tpost[i]] = {-f, -1}
//   scan .x with decoupled lookback; at tpre slots scatter final prefix
//   straight into y_node[node].  out[p] = y_node[node_of_pixel[p]].
// ---------------------------------------------------------------------------

#define TMAX     (1 << 20)          // 2N = 1,000,000 <= 1,048,576
#define NMAX     (1 << 19)          // N = 500,000 <= 524,288
#define STILE    8192
#define STHREADS 512
#define SIPT     (STILE / STHREADS) // 16 packed elems per thread

__device__ float2 g_pack[TMAX];     // .x = delta value, .y = node id bits
__device__ float  g_ynode[NMAX];
// [0] = ticket counter, [1..] = lookback descriptors (flag<<32 | float bits)
__device__ unsigned long long g_scan_state[256];

#define FLAG_AGG 1u
#define FLAG_PRE 2u

__device__ __forceinline__ unsigned long long pack_desc(float v, unsigned f) {
    return ((unsigned long long)f << 32) | (unsigned long long)__float_as_uint(v);
}

// --------------- kernel 1: filtered + packed scatter (+ state reset) -------
// Each thread handles node i and node i+half (two coalesced streams) for 2x
// memory-level parallelism on both the loads and the random scatters.
__global__ void k_filtered(const float* __restrict__ weight,
                           const float* __restrict__ bias,
                           const float* __restrict__ residues,
                           const float* __restrict__ attrs,
                           const int*   __restrict__ tpre,
                           const int*   __restrict__ tpost,
                           int n, int half, int nstate)
{
    if (blockIdx.x == 0 && threadIdx.x < nstate)
        g_scan_state[threadIdx.x] = 0ull;

    int i0 = blockIdx.x * blockDim.x + threadIdx.x;
    if (i0 >= half) return;
    int i1 = i0 + half;
    bool has1 = (i1 < n);

    float4 w0 = *reinterpret_cast<const float4*>(weight);
    float4 w1 = *(reinterpret_cast<const float4*>(weight) + 1);
    float  b0 = bias[0];

    // Stream 0
    const float4* a = reinterpret_cast<const float4*>(attrs + (size_t)i0 * 8);
    float4 p0 = a[0], p1 = a[1];
    float r0 = residues[i0];
    int   pre0 = tpre[i0], post0 = tpost[i0];

    // Stream 1
    float4 q0, q1;
    float r1 = 0.0f;
    int   pre1 = 0, post1 = 0;
    if (has1) {
        const float4* c = reinterpret_cast<const float4*>(attrs + (size_t)i1 * 8);
        q0 = c[0]; q1 = c[1];
        r1 = residues[i1];
        pre1 = tpre[i1]; post1 = tpost[i1];
    }

    float l0 = p0.x*w0.x + p0.y*w0.y + p0.z*w0.z + p0.w*w0.w
             + p1.x*w1.x + p1.y*w1.y + p1.z*w1.z + p1.w*w1.w + b0;
    float f0 = r0 * (1.0f / (1.0f + expf(-l0)));

    g_pack[pre0]  = make_float2( f0, __int_as_float(i0));
    g_pack[post0] = make_float2(-f0, __int_as_float(-1));

    if (has1) {
        float l1 = q0.x*w0.x + q0.y*w0.y + q0.z*w0.z + q0.w*w0.w
                 + q1.x*w1.x + q1.y*w1.y + q1.z*w1.z + q1.w*w1.w + b0;
        float f1 = r1 * (1.0f / (1.0f + expf(-l1)));
        g_pack[pre1]  = make_float2( f1, __int_as_float(i1));
        g_pack[post1] = make_float2(-f1, __int_as_float(-1));
    }
}

// ------- kernel 2: single-pass lookback scan + direct ynode scatter --------
__global__ __launch_bounds__(STHREADS) void k_scan(int T)
{
    __shared__ unsigned s_bid;
    __shared__ float    s_excl;
    __shared__ float    s_warp[STHREADS / 32];

    int t = threadIdx.x;
    int lane = t & 31;
    int w = t >> 5;

    if (t == 0) s_bid = atomicAdd((unsigned int*)&g_scan_state[0], 1u);
    __syncthreads();
    int b = (int)s_bid;
    unsigned long long* desc = g_scan_state + 1;

    int base = b * STILE;
    bool full = (base + STILE <= T);

    float e[SIPT];
    int   nd[SIPT];
    if (full) {
        const float4* src = reinterpret_cast<const float4*>(g_pack + base + t * SIPT);
#pragma unroll
        for (int q = 0; q < SIPT / 2; q++) {       // each float4 = 2 packed elems
            float4 v = src[q];
            e[q*2+0]  = v.x;  nd[q*2+0] = __float_as_int(v.y);
            e[q*2+1]  = v.z;  nd[q*2+1] = __float_as_int(v.w);
        }
    } else {
#pragma unroll
        for (int j = 0; j < SIPT; j++) {
            int g = base + t * SIPT + j;
            if (g < T) {
                float2 v = g_pack[g];
                e[j] = v.x;
                nd[j] = __float_as_int(v.y);
            } else {
                e[j] = 0.0f;
                nd[j] = -1;
            }
        }
    }

    float run = 0.0f;
#pragma unroll
    for (int j = 0; j < SIPT; j++) { run += e[j]; e[j] = run; }

    float incl = run;
#pragma unroll
    for (int o = 1; o < 32; o <<= 1) {
        float nb = __shfl_up_sync(0xffffffffu, incl, o);
        if (lane >= o) incl += nb;
    }
    if (lane == 31) s_warp[w] = incl;
    __syncthreads();
    if (t == 0) {
        float acc = 0.0f;
#pragma unroll
        for (int k = 0; k < STHREADS / 32; k++) { acc += s_warp[k]; s_warp[k] = acc; }
    }
    __syncthreads();
    float thr_excl = incl - run + (w > 0 ? s_warp[w - 1] : 0.0f);
    float block_total = s_warp[STHREADS / 32 - 1];

    if (t == 0) {
        unsigned long long d = (b == 0) ? pack_desc(block_total, FLAG_PRE)
                                        : pack_desc(block_total, FLAG_AGG);
        atomicExch(&desc[b], d);
        if (b == 0) s_excl = 0.0f;
    }

    if (b > 0 && w == 0) {
        float running = 0.0f;
        int tile_idx = b - 1;
        while (true) {
            int idx = tile_idx - lane;
            unsigned f;
            float val;
            if (idx < 0) { f = FLAG_PRE; val = 0.0f; }
            else {
                unsigned long long d;
                do {
                    d = *((volatile unsigned long long*)&desc[idx]);
                    f = (unsigned)(d >> 32);
                } while (f == 0u);
                val = __uint_as_float((unsigned)(d & 0xffffffffull));
            }
            unsigned pmask = __ballot_sync(0xffffffffu, f == FLAG_PRE);
            if (pmask) {
                int fp = __ffs(pmask) - 1;
                float c = (lane <= fp) ? val : 0.0f;
#pragma unroll
                for (int o = 16; o > 0; o >>= 1) c += __shfl_xor_sync(0xffffffffu, c, o);
                running += c;
                break;
            } else {
                float c = val;
#pragma unroll
                for (int o = 16; o > 0; o >>= 1) c += __shfl_xor_sync(0xffffffffu, c, o);
                running += c;
                tile_idx -= 32;
            }
        }
        if (lane == 0) {
            s_excl = running;
            atomicExch(&desc[b], pack_desc(running + block_total, FLAG_PRE));
        }
    }
    __syncthreads();
    float add = s_excl + thr_excl;

#pragma unroll
    for (int j = 0; j < SIPT; j++) {
        int node = nd[j];
        if (node >= 0) g_ynode[node] = e[j] + add;
    }
}

// ------------------------- kernel 3: per-pixel gather -----------------------
// 8 pixels/thread (best measured shape); 512-thread blocks; __ldg on table.
__global__ __launch_bounds__(512) void k_gather(const int* __restrict__ nop,
                                                float* __restrict__ out,
                                                int P)
{
    int i = (blockIdx.x * blockDim.x + threadIdx.x) * 8;
    if (i + 7 < P) {
        int4 n0 = *reinterpret_cast<const int4*>(nop + i);
        int4 n1 = *reinterpret_cast<const int4*>(nop + i + 4);
        float4 r0, r1;
        r0.x = __ldg(g_ynode + n0.x);
        r0.y = __ldg(g_ynode + n0.y);
        r0.z = __ldg(g_ynode + n0.z);
        r0.w = __ldg(g_ynode + n0.w);
        r1.x = __ldg(g_ynode + n1.x);
        r1.y = __ldg(g_ynode + n1.y);
        r1.z = __ldg(g_ynode + n1.z);
        r1.w = __ldg(g_ynode + n1.w);
        *reinterpret_cast<float4*>(out + i)     = r0;
        *reinterpret_cast<float4*>(out + i + 4) = r1;
    } else {
        for (int j = i; j < P; j++) out[j] = g_ynode[nop[j]];
    }
}

// ---------------------------------------------------------------------------
extern "C" void kernel_launch(void* const* d_in, const int* in_sizes, int n_in,
                              void* d_out, int out_size)
{
    const float* weight   = (const float*)d_in[0];
    const float* bias     = (const float*)d_in[1];
    const float* residues = (const float*)d_in[2];
    const float* attrs    = (const float*)d_in[3];
    const int*   tpre     = (const int*)d_in[4];
    const int*   tpost    = (const int*)d_in[5];
    const int*   nop      = (const int*)d_in[6];

    int N = in_sizes[2];
    int P = in_sizes[6];
    int T = 2 * N;
    int nb = (T + STILE - 1) / STILE;     // 123 blocks: single wave
    int half = (N + 1) / 2;

    k_filtered<<<(half + 255) / 256, 256>>>(weight, bias, residues, attrs,
                                            tpre, tpost, N, half, nb + 1);
    k_scan<<<nb, STHREADS>>>(T);

    int gt = (P + 7) / 8;
    k_gather<<<(gt + 511) / 512, 512>>>(nop, (float*)d_out, P);
}